// round 15
// baseline (speedup 1.0000x reference)
#include <cuda_runtime.h>
#include <cstdint>

#define B_  8
#define S_  512
#define E_  128
#define H_  512
#define BS_ (B_ * S_)      // 4096
#define O_  (E_ * E_)      // 16384

// wa global block list: 32 milestones (16 s each) x 128 o-tiles = 4096 blocks,
// s-ordered. Residency = 148 SMs x 3 CTAs = 444. Launch split in whole waves:
// 1332 / 1332 / 1332 / 100.
#define NWL 4
static const int WA_BASE[NWL]  = {0, 1332, 2664, 3996};
static const int WA_COUNT[NWL] = {1332, 1332, 1332, 100};
// recur chunk c = [RS[c], RS[c+1]), gated on wa launch c.
// L0 completes milestones 0..9  (s<160)  >= 144
// L1 completes milestones ..19  (s<320)  >= 288
// L2 completes milestones ..30  (s<496)
static const int RS[NWL + 1] = {0, 144, 288, 496, 512};

// Persistent scratch (static __device__ — no runtime allocation)
__device__ float g_hidden[BS_ * H_];                 // 8 MB   [bs][h]
__device__ float g_W2T[O_ * H_];                     // 32 MB  tile-contiguous [k][o]
__device__ float g_Wa[(size_t)BS_ * O_];             // 268 MB [bs][o], o = d*128+e
__device__ float g_et[B_ * E_];                      // et carried across chunks

// ---------------------------------------------------------------------------
// XLA/Eigen fast tanh for f32 — exact coefficients and op order (bit-critical)
// ---------------------------------------------------------------------------
__device__ __forceinline__ float tanh_xla(float x) {
    const float kClamp = 7.90531110763549805f;
    float ax = fabsf(x);
    float xc = fmaxf(-kClamp, fminf(kClamp, x));
    float x2 = xc * xc;
    float p = fmaf(x2, -2.76076847742355e-16f, 2.00018790482477e-13f);
    p = fmaf(x2, p, -8.60467152213735e-11f);
    p = fmaf(x2, p,  5.12229709037114e-08f);
    p = fmaf(x2, p,  1.48572235717979e-05f);
    p = fmaf(x2, p,  6.37261928875436e-04f);
    p = fmaf(x2, p,  4.89352455891786e-03f);
    p = xc * p;
    float q = fmaf(x2, 1.19825839466702e-06f, 1.18534705686654e-04f);
    q = fmaf(x2, q, 2.26843463243900e-03f);
    q = fmaf(x2, q, 4.89352518554385e-03f);
    float r = p / q;
    return (ax < 0.0004f) ? x : r;
}

// ---------------------------------------------------------------------------
// packed f32x2 helpers (bitwise: IEEE fma per 32-bit half; pairing is across
// two DIFFERENT outputs — each output's chain stays one sequential chain)
// ---------------------------------------------------------------------------
__device__ __forceinline__ void ffma2_(unsigned long long& d,
                                       unsigned long long a,
                                       unsigned long long b) {
    asm("fma.rn.f32x2 %0, %1, %2, %0;" : "+l"(d) : "l"(a), "l"(b));
}
__device__ __forceinline__ unsigned long long dupf_(float x) {
    unsigned long long r;
    unsigned u = __float_as_uint(x);
    asm("mov.b64 %0, {%1, %1};" : "=l"(r) : "r"(u));
    return r;
}
__device__ __forceinline__ float lo_(unsigned long long a) {
    return __uint_as_float((unsigned)(a & 0xffffffffull));
}
__device__ __forceinline__ float hi_(unsigned long long a) {
    return __uint_as_float((unsigned)(a >> 32));
}

// ---------------------------------------------------------------------------
// async-copy / mbarrier helpers
// ---------------------------------------------------------------------------
__device__ __forceinline__ void cp_async16_(uint32_t dst, const void* src) {
    asm volatile("cp.async.cg.shared.global [%0], [%1], 16;"
                 :: "r"(dst), "l"(src) : "memory");
}
__device__ __forceinline__ void cp_commit_() {
    asm volatile("cp.async.commit_group;" ::: "memory");
}
__device__ __forceinline__ void cp_wait0_() {
    asm volatile("cp.async.wait_group 0;" ::: "memory");
}
__device__ __forceinline__ void mbar_init_(uint32_t a, uint32_t cnt) {
    asm volatile("mbarrier.init.shared.b64 [%0], %1;" :: "r"(a), "r"(cnt) : "memory");
}
__device__ __forceinline__ void mbar_expect_tx_(uint32_t a, uint32_t bytes) {
    asm volatile("mbarrier.arrive.expect_tx.shared.b64 _, [%0], %1;"
                 :: "r"(a), "r"(bytes) : "memory");
}
__device__ __forceinline__ void bulk_g2s_(uint32_t dst, const void* src,
                                          uint32_t bytes, uint32_t mbar) {
    asm volatile("cp.async.bulk.shared::cluster.global.mbarrier::complete_tx::bytes "
                 "[%0], [%1], %2, [%3];"
                 :: "r"(dst), "l"(src), "r"(bytes), "r"(mbar) : "memory");
}
__device__ __forceinline__ void mbar_wait_(uint32_t a, uint32_t parity) {
    asm volatile(
        "{\n\t.reg .pred P;\n\t"
        "WL%=:\n\t"
        "mbarrier.try_wait.parity.acquire.cta.shared::cta.b64 P, [%0], %1, 0x989680;\n\t"
        "@P bra WD%=;\n\t"
        "bra WL%=;\n\t"
        "WD%=:\n\t}"
        :: "r"(a), "r"(parity) : "memory");
}

// ---------------------------------------------------------------------------
// Kernel 0: W2 -> tile-contiguous transposed copy.
// Tile (ot, it) = [k in it*32..+32) x [o in ot*128..+128), stored contiguous:
//   g_W2T[((ot*16 + it)*32 + k)*128 + (o - ot*128)] = W2[o][it*32 + k]
// Pure data movement (64 MB traffic, ~16us). Enables cp.async staging in wa.
// ---------------------------------------------------------------------------
__global__ void w2t_kernel(const float* __restrict__ W2) {
    const int ot = blockIdx.x;        // 0..127
    const int it = blockIdx.y;        // 0..15
    const int tid = threadIdx.x;      // 0..255
    const int op  = tid >> 1;         // o within tile 0..127
    const int sk  = (tid & 1) * 16;   // k seg 0 or 16

    const float* src = W2 + (size_t)(ot * 128 + op) * H_ + it * 32 + sk;
    float* dst = g_W2T + ((size_t)(ot * 16 + it) * 32) * 128;
#pragma unroll
    for (int v = 0; v < 4; v++) {
        float4 a = *(const float4*)(src + v * 4);
        dst[(sk + v * 4 + 0) * 128 + op] = a.x;
        dst[(sk + v * 4 + 1) * 128 + op] = a.y;
        dst[(sk + v * 4 + 2) * 128 + op] = a.z;
        dst[(sk + v * 4 + 3) * 128 + op] = a.w;
    }
}

// ---------------------------------------------------------------------------
// Kernel 1: hidden (unchanged — 55us)
// ---------------------------------------------------------------------------
#define HROWS 32
#define XPAD  36

__global__ void __launch_bounds__(512, 1)
hidden_kernel(const float* __restrict__ X,
              const float* __restrict__ W1,
              const float* __restrict__ b1) {
    extern __shared__ float sh[];
    float* x_s = sh;                    // [E_][XPAD]
    float* w1t = sh + E_ * XPAD;        // [32][512]

    const int row0 = blockIdx.x * HROWS;
    const int t    = threadIdx.x;       // h = t

    {
        const int r  = t & 31;
        const int e0 = (t >> 5) * 8;
        const float* src = X + (size_t)(row0 + r) * E_ + e0;
        float4 a = *(const float4*)src;
        float4 c = *(const float4*)(src + 4);
        x_s[(e0 + 0) * XPAD + r] = a.x; x_s[(e0 + 1) * XPAD + r] = a.y;
        x_s[(e0 + 2) * XPAD + r] = a.z; x_s[(e0 + 3) * XPAD + r] = a.w;
        x_s[(e0 + 4) * XPAD + r] = c.x; x_s[(e0 + 5) * XPAD + r] = c.y;
        x_s[(e0 + 6) * XPAD + r] = c.z; x_s[(e0 + 7) * XPAD + r] = c.w;
    }

    float acc[HROWS];
#pragma unroll
    for (int r = 0; r < HROWS; r++) acc[r] = 0.f;

    float4 w4[8];
    {
        const float* wsrc = W1 + (size_t)t * E_;
#pragma unroll
        for (int v = 0; v < 8; v++) w4[v] = ((const float4*)wsrc)[v];
    }

    for (int ec = 0; ec < E_; ec += 32) {
        __syncthreads();
#pragma unroll
        for (int v = 0; v < 8; v++) {
            w1t[(v * 4 + 0) * 512 + t] = w4[v].x;
            w1t[(v * 4 + 1) * 512 + t] = w4[v].y;
            w1t[(v * 4 + 2) * 512 + t] = w4[v].z;
            w1t[(v * 4 + 3) * 512 + t] = w4[v].w;
        }
        __syncthreads();
        if (ec + 32 < E_) {
            const float* wsrc = W1 + (size_t)t * E_ + ec + 32;
#pragma unroll
            for (int v = 0; v < 8; v++) w4[v] = ((const float4*)wsrc)[v];
        }
#pragma unroll 4
        for (int de = 0; de < 32; de++) {      // e ascending — order-critical
            float wv = w1t[de * 512 + t];
            const float* xrow = x_s + (ec + de) * XPAD;
#pragma unroll
            for (int j = 0; j < 8; j++) {
                float4 xv = *(const float4*)(xrow + 4 * j);
                acc[4 * j + 0] = fmaf(xv.x, wv, acc[4 * j + 0]);
                acc[4 * j + 1] = fmaf(xv.y, wv, acc[4 * j + 1]);
                acc[4 * j + 2] = fmaf(xv.z, wv, acc[4 * j + 2]);
                acc[4 * j + 3] = fmaf(xv.w, wv, acc[4 * j + 3]);
            }
        }
    }

    const float bias = b1[t];
#pragma unroll 4
    for (int r = 0; r < HROWS; r++)
        g_hidden[(size_t)(row0 + r) * H_ + t] = tanh_xla(acc[r] + bias);
}

#define HID_SMEM ((E_ * XPAD + 32 * 512) * 4)   // 83968 bytes

// ---------------------------------------------------------------------------
// Kernel 2: Wa[bs][o] = (seq-h FFMA2 chain) + b2[o]
// k-loop geometry IDENTICAL to round 6/13. Changes: both tiles staged via
// cp.async (w from pre-transposed g_W2T — frees 16 staging regs + removes
// transpose STS), and 3 CTAs/SM via __launch_bounds__(256,3) for 24 warps/SM.
// Accumulation: k strictly ascending, one chain per output — order-critical.
// ---------------------------------------------------------------------------
#define BO  128
#define KC  32
#define NT  (H_ / KC)   // 16 tiles

__global__ void __launch_bounds__(256, 3)
wa_kernel(const float* __restrict__ b2, int base) {
    __shared__ __align__(16) float w_s[2][KC][BO];    // 2 x 16 KB, [k][o]
    __shared__ __align__(16) float h_s[2][BO][KC];    // 2 x 16 KB, [row][k]

    const int flat  = base + blockIdx.x;
    const int s0    = (flat >> 7) * 16;       // milestone start s
    const int ot    = flat & 127;             // o-tile index
    const int obase = ot * BO;
    const int tid   = threadIdx.x;
    const int to = tid & 15;     // o  pairs: 2*to + 32*i
    const int tb = tid >> 4;     // row pairs: 2*tb + 32*j

    unsigned long long accp[4][8];
#pragma unroll
    for (int i = 0; i < 4; i++)
#pragma unroll
        for (int j = 0; j < 8; j++) accp[i][j] = 0ull;

    const uint32_t w_smem0 = (uint32_t)__cvta_generic_to_shared(&w_s[0][0][0]);
    const uint32_t h_smem0 = (uint32_t)__cvta_generic_to_shared(&h_s[0][0][0]);
    const float*   wt_base = g_W2T + (size_t)ot * (16 * 32 * 128);

    // tile row -> global bs row:  b = row>>4,  s = s0 + (row&15)
    auto bs_row = [&](int row) -> int { return ((row >> 4) * S_) + s0 + (row & 15); };

    // stage both tiles for k-tile 'it' into buffer 'buf' (one commit group)
    auto stage = [&](int buf, int it) {
        const float* wsrc = wt_base + (size_t)it * (32 * 128);
#pragma unroll
        for (int q = 0; q < 4; q++) {
            int id = q * 256 + tid;                    // 0..1023
            cp_async16_(w_smem0 + (buf * KC * BO + id * 4) * 4, wsrc + id * 4);
        }
#pragma unroll
        for (int q = 0; q < 4; q++) {
            int id   = q * 256 + tid;
            int row  = id >> 3;                        // 0..127
            int c16  = (id & 7) * 4;                   // float offset in row
            const float* src = g_hidden + (size_t)bs_row(row) * H_ + it * KC + c16;
            cp_async16_(h_smem0 + ((buf * BO + row) * KC + c16) * 4, src);
        }
        cp_commit_();
    };

    stage(0, 0);   // prologue

    for (int it = 0; it < NT; it++) {
        const int cur = it & 1;
        cp_wait0_();              // tile 'it' arrived (only outstanding group)
        __syncthreads();          // visible to all; prev buffer free

        if (it + 1 < NT) stage(cur ^ 1, it + 1);   // prefetch under k-loop

#pragma unroll 4
        for (int k = 0; k < KC; k++) {   // k strictly ascending — order-critical
            unsigned long long wv2[4];
#pragma unroll
            for (int i = 0; i < 4; i++)
                wv2[i] = *(const unsigned long long*)&w_s[cur][k][2 * to + 32 * i];
#pragma unroll
            for (int j = 0; j < 4; j++) {
                unsigned long long dl = dupf_(h_s[cur][2 * tb + 32 * j + 0][k]);
                unsigned long long dh = dupf_(h_s[cur][2 * tb + 32 * j + 1][k]);
#pragma unroll
                for (int i = 0; i < 4; i++) {
                    ffma2_(accp[i][2 * j + 0], wv2[i], dl);
                    ffma2_(accp[i][2 * j + 1], wv2[i], dh);
                }
            }
        }
        __syncthreads();          // k-loop done before next overwrite
    }

    // epilogue: + b2, float2 stores
#pragma unroll
    for (int i = 0; i < 4; i++) {
        int o0 = obase + 2 * to + 32 * i;
        float blo = b2[o0];
        float bhi = b2[o0 + 1];
#pragma unroll
        for (int j = 0; j < 4; j++) {
#pragma unroll
            for (int half = 0; half < 2; half++) {
                int row = 2 * tb + 32 * j + half;
                int bs  = bs_row(row);
                unsigned long long a = accp[i][2 * j + half];
                float2 res = make_float2(lo_(a) + blo, hi_(a) + bhi);
                *(float2*)&g_Wa[(size_t)bs * O_ + o0] = res;
            }
        }
    }
}

// ---------------------------------------------------------------------------
// Kernel 3 (chunked, arbitrary [s_begin, s_end)): recurrence (unchanged).
// et carried via g_et (exact fp32 pass-through). seq-d chain, clip.
// ---------------------------------------------------------------------------
#define STAGES 3
#define TILE_BYTES_R (O_ * 4)   // 65536

__global__ void __launch_bounds__(E_, 1)
recur_kernel(const float* __restrict__ e0, float* __restrict__ out,
             int s_begin_raw, int s_end) {
    extern __shared__ float wa_buf[];            // STAGES * O_ floats (192 KB)
    __shared__ float et_s[E_];
    __shared__ __align__(8) unsigned long long mbar[STAGES];

    const int b = blockIdx.x;      // 0..7
    const int e = threadIdx.x;     // 0..127

    uint32_t mb[STAGES];
#pragma unroll
    for (int i = 0; i < STAGES; i++)
        mb[i] = (uint32_t)__cvta_generic_to_shared(&mbar[i]);

    if (e == 0) {
#pragma unroll
        for (int i = 0; i < STAGES; i++) mbar_init_(mb[i], 1);
    }

    const int s_begin = (s_begin_raw == 0) ? 1 : s_begin_raw;

    float v;
    if (s_begin_raw == 0) {
        v = e0[e];
        out[((size_t)b * S_ + 0) * E_ + e] = v;
    } else {
        v = g_et[b * E_ + e];
    }
    et_s[e] = v;
    __syncthreads();   // mbar init + et_s visible

    const float* wa_base = g_Wa + (size_t)b * S_ * O_;

    if (e == 0) {
#pragma unroll
        for (int i = 0; i < STAGES; i++) {
            if (s_begin + i < s_end) {
                mbar_expect_tx_(mb[i], TILE_BYTES_R);
                bulk_g2s_((uint32_t)__cvta_generic_to_shared(&wa_buf[i * O_]),
                          wa_base + (size_t)(s_begin + i) * O_, TILE_BYTES_R, mb[i]);
            }
        }
    }

    for (int s = s_begin; s < s_end; s++) {
        const int      i      = s - s_begin;
        const int      slot   = i % STAGES;
        const uint32_t parity = (uint32_t)((i / STAGES) & 1);
        mbar_wait_(mb[slot], parity);

        const float* buf = wa_buf + slot * O_;
        float acc = 0.f;
#pragma unroll 16
        for (int d = 0; d < E_; d++)           // d ascending — order-critical
            acc = fmaf(et_s[d], buf[d * E_ + e], acc);
        float nv = fminf(5.0f, fmaxf(-5.0f, acc));
        out[((size_t)b * S_ + s) * E_ + e] = nv;

        __syncthreads();                       // all done reading buf & et_s
        et_s[e] = nv;
        if (e == 0 && s + STAGES < s_end) {
            mbar_expect_tx_(mb[slot], TILE_BYTES_R);
            bulk_g2s_((uint32_t)__cvta_generic_to_shared(&wa_buf[slot * O_]),
                      wa_base + (size_t)(s + STAGES) * O_, TILE_BYTES_R, mb[slot]);
        }
        __syncthreads();                       // et_s published
        v = nv;
    }

    g_et[b * E_ + e] = v;                      // exact fp32 pass-through
}

// ---------------------------------------------------------------------------
// Launch: CAPTURE-LEGAL fork — ev_fork recorded on the origin stream BEFORE
// any side-stream work (this was round-13's failure). Then: w2t on s2 ∥
// hidden on origin; origin joins ev_t; wa launches serialized (whole-wave
// sizes) with per-launch events; recur chunks on s2 gated on wa events; join.
// ---------------------------------------------------------------------------
extern "C" void kernel_launch(void* const* d_in, const int* in_sizes, int n_in,
                              void* d_out, int out_size) {
    const float* X  = (const float*)d_in[0];   // [8,512,128]
    const float* W1 = (const float*)d_in[1];   // [512,128]
    const float* b1 = (const float*)d_in[2];   // [512]
    const float* W2 = (const float*)d_in[3];   // [16384,512]
    const float* b2 = (const float*)d_in[4];   // [16384]
    const float* e0 = (const float*)d_in[5];   // [1,128]
    float* out = (float*)d_out;                // [8,512,128] float32

    static cudaStream_t s2 = nullptr;
    static cudaEvent_t  ev_fork, ev_t;
    static cudaEvent_t  ev_wa[NWL];
    static cudaEvent_t  ev_join;
    if (s2 == nullptr) {
        cudaStreamCreateWithFlags(&s2, cudaStreamNonBlocking);
        cudaEventCreateWithFlags(&ev_fork, cudaEventDisableTiming);
        cudaEventCreateWithFlags(&ev_t, cudaEventDisableTiming);
        for (int c = 0; c < NWL; c++)
            cudaEventCreateWithFlags(&ev_wa[c], cudaEventDisableTiming);
        cudaEventCreateWithFlags(&ev_join, cudaEventDisableTiming);
        cudaFuncSetAttribute(hidden_kernel,
                             cudaFuncAttributeMaxDynamicSharedMemorySize, HID_SMEM);
        cudaFuncSetAttribute(recur_kernel,
                             cudaFuncAttributeMaxDynamicSharedMemorySize,
                             STAGES * TILE_BYTES_R);
    }

    // Fork FIRST from the origin (capture) stream, THEN use s2.
    cudaEventRecord(ev_fork, 0);
    cudaStreamWaitEvent(s2, ev_fork, 0);

    // W2 transpose on s2 overlaps hidden on origin stream
    w2t_kernel<<<dim3(128, 16), 256, 0, s2>>>(W2);
    cudaEventRecord(ev_t, s2);

    hidden_kernel<<<BS_ / HROWS, 512, HID_SMEM>>>(X, W1, b1);
    cudaStreamWaitEvent(0, ev_t, 0);

    for (int c = 0; c < NWL; c++) {
        wa_kernel<<<WA_COUNT[c], 256>>>(b2, WA_BASE[c]);
        cudaEventRecord(ev_wa[c], 0);
    }
    for (int c = 0; c < NWL; c++) {
        cudaStreamWaitEvent(s2, ev_wa[c], 0);
        recur_kernel<<<B_, E_, STAGES * TILE_BYTES_R, s2>>>(e0, out, RS[c], RS[c + 1]);
    }
    cudaEventRecord(ev_join, s2);
    cudaStreamWaitEvent(0, ev_join, 0);
}

// round 16
// speedup vs baseline: 3.9513x; 3.9513x over previous
#include <cuda_runtime.h>
#include <cstdint>

#define B_  8
#define S_  512
#define E_  128
#define H_  512
#define BS_ (B_ * S_)      // 4096
#define O_  (E_ * E_)      // 16384

// wa global block list: 32 milestones (16 s each) x 128 o-tiles = 4096 blocks,
// s-ordered. Residency = 148 SMs x 2 CTAs = 296. Launch split (14 waves):
// 1184 / 1184 / 1184 / 296 / 248.
#define NWL 5
static const int WA_BASE[NWL]  = {0, 1184, 2368, 3552, 3848};
static const int WA_COUNT[NWL] = {1184, 1184, 1184, 296, 248};
// recur chunk c = [RS[c], RS[c+1]), gated on wa launch c.
// cumulative blocks 1184/2368/3552/3848/4096 complete milestones
// through s<160/320/432/480/512 -> safe gates 144/288/432/480/512.
static const int RS[NWL + 1] = {0, 144, 288, 432, 480, 512};

// Persistent scratch (static __device__ — no runtime allocation)
__device__ float g_hidden[BS_ * H_];                 // 8 MB   [bs][h]
__device__ float g_Wa[(size_t)BS_ * O_];             // 268 MB [bs][o], o = d*128+e
__device__ float g_et[B_ * E_];                      // et carried across chunks

// ---------------------------------------------------------------------------
// XLA/Eigen fast tanh for f32 — exact coefficients and op order (bit-critical)
// ---------------------------------------------------------------------------
__device__ __forceinline__ float tanh_xla(float x) {
    const float kClamp = 7.90531110763549805f;
    float ax = fabsf(x);
    float xc = fmaxf(-kClamp, fminf(kClamp, x));
    float x2 = xc * xc;
    float p = fmaf(x2, -2.76076847742355e-16f, 2.00018790482477e-13f);
    p = fmaf(x2, p, -8.60467152213735e-11f);
    p = fmaf(x2, p,  5.12229709037114e-08f);
    p = fmaf(x2, p,  1.48572235717979e-05f);
    p = fmaf(x2, p,  6.37261928875436e-04f);
    p = fmaf(x2, p,  4.89352455891786e-03f);
    p = xc * p;
    float q = fmaf(x2, 1.19825839466702e-06f, 1.18534705686654e-04f);
    q = fmaf(x2, q, 2.26843463243900e-03f);
    q = fmaf(x2, q, 4.89352518554385e-03f);
    float r = p / q;
    return (ax < 0.0004f) ? x : r;
}

// ---------------------------------------------------------------------------
// packed f32x2 helpers (bitwise: IEEE fma per 32-bit half; pairing is across
// two DIFFERENT outputs — each output's chain stays one sequential chain)
// ---------------------------------------------------------------------------
__device__ __forceinline__ void ffma2_(unsigned long long& d,
                                       unsigned long long a,
                                       unsigned long long b) {
    asm("fma.rn.f32x2 %0, %1, %2, %0;" : "+l"(d) : "l"(a), "l"(b));
}
__device__ __forceinline__ unsigned long long dupf_(float x) {
    unsigned long long r;
    unsigned u = __float_as_uint(x);
    asm("mov.b64 %0, {%1, %1};" : "=l"(r) : "r"(u));
    return r;
}
__device__ __forceinline__ float lo_(unsigned long long a) {
    return __uint_as_float((unsigned)(a & 0xffffffffull));
}
__device__ __forceinline__ float hi_(unsigned long long a) {
    return __uint_as_float((unsigned)(a >> 32));
}

// ---------------------------------------------------------------------------
// async-copy / mbarrier helpers
// ---------------------------------------------------------------------------
__device__ __forceinline__ void cp_async16_(uint32_t dst, const void* src) {
    asm volatile("cp.async.cg.shared.global [%0], [%1], 16;"
                 :: "r"(dst), "l"(src) : "memory");
}
__device__ __forceinline__ void cp_commit_() {
    asm volatile("cp.async.commit_group;" ::: "memory");
}
__device__ __forceinline__ void cp_wait0_() {
    asm volatile("cp.async.wait_group 0;" ::: "memory");
}
__device__ __forceinline__ void mbar_init_(uint32_t a, uint32_t cnt) {
    asm volatile("mbarrier.init.shared.b64 [%0], %1;" :: "r"(a), "r"(cnt) : "memory");
}
__device__ __forceinline__ void mbar_expect_tx_(uint32_t a, uint32_t bytes) {
    asm volatile("mbarrier.arrive.expect_tx.shared.b64 _, [%0], %1;"
                 :: "r"(a), "r"(bytes) : "memory");
}
__device__ __forceinline__ void bulk_g2s_(uint32_t dst, const void* src,
                                          uint32_t bytes, uint32_t mbar) {
    asm volatile("cp.async.bulk.shared::cluster.global.mbarrier::complete_tx::bytes "
                 "[%0], [%1], %2, [%3];"
                 :: "r"(dst), "l"(src), "r"(bytes), "r"(mbar) : "memory");
}
__device__ __forceinline__ void mbar_wait_(uint32_t a, uint32_t parity) {
    asm volatile(
        "{\n\t.reg .pred P;\n\t"
        "WL%=:\n\t"
        "mbarrier.try_wait.parity.acquire.cta.shared::cta.b64 P, [%0], %1, 0x989680;\n\t"
        "@P bra WD%=;\n\t"
        "bra WL%=;\n\t"
        "WD%=:\n\t}"
        :: "r"(a), "r"(parity) : "memory");
}

// ---------------------------------------------------------------------------
// Kernel 1: hidden (unchanged — 55us)
// ---------------------------------------------------------------------------
#define HROWS 32
#define XPAD  36

__global__ void __launch_bounds__(512, 1)
hidden_kernel(const float* __restrict__ X,
              const float* __restrict__ W1,
              const float* __restrict__ b1) {
    extern __shared__ float sh[];
    float* x_s = sh;                    // [E_][XPAD]
    float* w1t = sh + E_ * XPAD;        // [32][512]

    const int row0 = blockIdx.x * HROWS;
    const int t    = threadIdx.x;       // h = t

    {
        const int r  = t & 31;
        const int e0 = (t >> 5) * 8;
        const float* src = X + (size_t)(row0 + r) * E_ + e0;
        float4 a = *(const float4*)src;
        float4 c = *(const float4*)(src + 4);
        x_s[(e0 + 0) * XPAD + r] = a.x; x_s[(e0 + 1) * XPAD + r] = a.y;
        x_s[(e0 + 2) * XPAD + r] = a.z; x_s[(e0 + 3) * XPAD + r] = a.w;
        x_s[(e0 + 4) * XPAD + r] = c.x; x_s[(e0 + 5) * XPAD + r] = c.y;
        x_s[(e0 + 6) * XPAD + r] = c.z; x_s[(e0 + 7) * XPAD + r] = c.w;
    }

    float acc[HROWS];
#pragma unroll
    for (int r = 0; r < HROWS; r++) acc[r] = 0.f;

    float4 w4[8];
    {
        const float* wsrc = W1 + (size_t)t * E_;
#pragma unroll
        for (int v = 0; v < 8; v++) w4[v] = ((const float4*)wsrc)[v];
    }

    for (int ec = 0; ec < E_; ec += 32) {
        __syncthreads();
#pragma unroll
        for (int v = 0; v < 8; v++) {
            w1t[(v * 4 + 0) * 512 + t] = w4[v].x;
            w1t[(v * 4 + 1) * 512 + t] = w4[v].y;
            w1t[(v * 4 + 2) * 512 + t] = w4[v].z;
            w1t[(v * 4 + 3) * 512 + t] = w4[v].w;
        }
        __syncthreads();
        if (ec + 32 < E_) {
            const float* wsrc = W1 + (size_t)t * E_ + ec + 32;
#pragma unroll
            for (int v = 0; v < 8; v++) w4[v] = ((const float4*)wsrc)[v];
        }
#pragma unroll 4
        for (int de = 0; de < 32; de++) {      // e ascending — order-critical
            float wv = w1t[de * 512 + t];
            const float* xrow = x_s + (ec + de) * XPAD;
#pragma unroll
            for (int j = 0; j < 8; j++) {
                float4 xv = *(const float4*)(xrow + 4 * j);
                acc[4 * j + 0] = fmaf(xv.x, wv, acc[4 * j + 0]);
                acc[4 * j + 1] = fmaf(xv.y, wv, acc[4 * j + 1]);
                acc[4 * j + 2] = fmaf(xv.z, wv, acc[4 * j + 2]);
                acc[4 * j + 3] = fmaf(xv.w, wv, acc[4 * j + 3]);
            }
        }
    }

    const float bias = b1[t];
#pragma unroll 4
    for (int r = 0; r < HROWS; r++)
        g_hidden[(size_t)(row0 + r) * H_ + t] = tanh_xla(acc[r] + bias);
}

#define HID_SMEM ((E_ * XPAD + 32 * 512) * 4)   // 83968 bytes

// ---------------------------------------------------------------------------
// Kernel 2: Wa[bs][o] = (seq-h FFMA2 chain) + b2[o]
// EXACT round-6/13 inner loop (2 CTAs/SM, register-staged w, cp.async h).
// Milestone bs map: flat block -> milestone m (16 s x 8 b) + o-tile; tile row
// r -> bs = (r>>4)*512 + 16*m + (r&15). Each (bs,o) output keeps its single
// k-ascending FMA chain — bitwise identical.
// ---------------------------------------------------------------------------
#define BO  128
#define KC  32
#define NT  (H_ / KC)   // 16 tiles

__global__ void __launch_bounds__(256, 2)
wa_kernel(const float* __restrict__ W2, const float* __restrict__ b2, int base) {
    __shared__ __align__(16) float w_s[2][KC][BO];    // 2 x 16 KB, [k][o]
    __shared__ __align__(16) float h_s[2][BO][KC];    // 2 x 16 KB, [row][k]

    const int flat  = base + blockIdx.x;
    const int s0    = (flat >> 7) * 16;       // milestone start s
    const int obase = (flat & 127) * BO;
    const int tid   = threadIdx.x;
    const int to = tid & 15;     // o  pairs: 2*to + 32*i
    const int tb = tid >> 4;     // row pairs: 2*tb + 32*j

    unsigned long long accp[4][8];
#pragma unroll
    for (int i = 0; i < 4; i++)
#pragma unroll
        for (int j = 0; j < 8; j++) accp[i][j] = 0ull;

    const int r   = tid >> 1;          // tile row 0..127
    const int seg = (tid & 1) * 16;    // 16 k-values per thread (w staging)

    const float*    wsrc0   = W2 + (size_t)(obase + r) * H_ + seg;
    const uint32_t  h_smem0 = (uint32_t)__cvta_generic_to_shared(&h_s[0][0][0]);

    // tile row -> global bs row:  b = row>>4,  s = s0 + (row&15)
    auto bs_row = [&](int row) -> int { return ((row >> 4) * S_) + s0 + (row & 15); };

    // h cp.async: 1024 16B chunks per tile, 4 per thread
    auto stage_h = [&](int buf, int kc) {
#pragma unroll
        for (int q = 0; q < 4; q++) {
            int id   = q * 256 + tid;
            int row  = id >> 3;            // 0..127
            int c16  = (id & 7) * 4;       // float offset within row
            const float* src = g_hidden + (size_t)bs_row(row) * H_ + kc + c16;
            uint32_t dst = h_smem0 + ((buf * BO + row) * KC + c16) * 4;
            cp_async16_(dst, src);
        }
        cp_commit_();
    };

    // prologue: tile 0
    stage_h(0, 0);
    float4 wreg[4];
#pragma unroll
    for (int v = 0; v < 4; v++) wreg[v] = *(const float4*)(wsrc0 + v * 4);

    for (int it = 0; it < NT; it++) {
        const int cur = it & 1;
        // store w tile it (transposed) — w_s[cur] free: last read at it-2
#pragma unroll
        for (int v = 0; v < 4; v++) {
            w_s[cur][seg + v * 4 + 0][r] = wreg[v].x;
            w_s[cur][seg + v * 4 + 1][r] = wreg[v].y;
            w_s[cur][seg + v * 4 + 2][r] = wreg[v].z;
            w_s[cur][seg + v * 4 + 3][r] = wreg[v].w;
        }
        cp_wait0_();              // this thread's h tile 'it' copies done
        __syncthreads();          // everyone's h + w visible; prev bufs free

        if (it + 1 < NT) {        // start next tile: latency hides under k-loop
            stage_h(cur ^ 1, (it + 1) * KC);
#pragma unroll
            for (int v = 0; v < 4; v++)
                wreg[v] = *(const float4*)(wsrc0 + (it + 1) * KC + v * 4);
        }

#pragma unroll 4
        for (int k = 0; k < KC; k++) {   // k strictly ascending — order-critical
            unsigned long long wv2[4];
#pragma unroll
            for (int i = 0; i < 4; i++)
                wv2[i] = *(const unsigned long long*)&w_s[cur][k][2 * to + 32 * i];
#pragma unroll
            for (int j = 0; j < 4; j++) {
                unsigned long long dl = dupf_(h_s[cur][2 * tb + 32 * j + 0][k]);
                unsigned long long dh = dupf_(h_s[cur][2 * tb + 32 * j + 1][k]);
#pragma unroll
                for (int i = 0; i < 4; i++) {
                    ffma2_(accp[i][2 * j + 0], wv2[i], dl);
                    ffma2_(accp[i][2 * j + 1], wv2[i], dh);
                }
            }
        }
    }

    // epilogue: + b2, float2 stores
#pragma unroll
    for (int i = 0; i < 4; i++) {
        int o0 = obase + 2 * to + 32 * i;
        float blo = b2[o0];
        float bhi = b2[o0 + 1];
#pragma unroll
        for (int j = 0; j < 4; j++) {
#pragma unroll
            for (int half = 0; half < 2; half++) {
                int row = 2 * tb + 32 * j + half;
                int bs  = bs_row(row);
                unsigned long long a = accp[i][2 * j + half];
                float2 res = make_float2(lo_(a) + blo, hi_(a) + bhi);
                *(float2*)&g_Wa[(size_t)bs * O_ + o0] = res;
            }
        }
    }
}

// ---------------------------------------------------------------------------
// Kernel 3 (chunked, arbitrary [s_begin, s_end)): recurrence (unchanged).
// et carried via g_et (exact fp32 pass-through). seq-d chain, clip.
// ---------------------------------------------------------------------------
#define STAGES 3
#define TILE_BYTES_R (O_ * 4)   // 65536

__global__ void __launch_bounds__(E_, 1)
recur_kernel(const float* __restrict__ e0, float* __restrict__ out,
             int s_begin_raw, int s_end) {
    extern __shared__ float wa_buf[];            // STAGES * O_ floats (192 KB)
    __shared__ float et_s[E_];
    __shared__ __align__(8) unsigned long long mbar[STAGES];

    const int b = blockIdx.x;      // 0..7
    const int e = threadIdx.x;     // 0..127

    uint32_t mb[STAGES];
#pragma unroll
    for (int i = 0; i < STAGES; i++)
        mb[i] = (uint32_t)__cvta_generic_to_shared(&mbar[i]);

    if (e == 0) {
#pragma unroll
        for (int i = 0; i < STAGES; i++) mbar_init_(mb[i], 1);
    }

    const int s_begin = (s_begin_raw == 0) ? 1 : s_begin_raw;

    float v;
    if (s_begin_raw == 0) {
        v = e0[e];
        out[((size_t)b * S_ + 0) * E_ + e] = v;
    } else {
        v = g_et[b * E_ + e];
    }
    et_s[e] = v;
    __syncthreads();   // mbar init + et_s visible

    const float* wa_base = g_Wa + (size_t)b * S_ * O_;

    if (e == 0) {
#pragma unroll
        for (int i = 0; i < STAGES; i++) {
            if (s_begin + i < s_end) {
                mbar_expect_tx_(mb[i], TILE_BYTES_R);
                bulk_g2s_((uint32_t)__cvta_generic_to_shared(&wa_buf[i * O_]),
                          wa_base + (size_t)(s_begin + i) * O_, TILE_BYTES_R, mb[i]);
            }
        }
    }

    for (int s = s_begin; s < s_end; s++) {
        const int      i      = s - s_begin;
        const int      slot   = i % STAGES;
        const uint32_t parity = (uint32_t)((i / STAGES) & 1);
        mbar_wait_(mb[slot], parity);

        const float* buf = wa_buf + slot * O_;
        float acc = 0.f;
#pragma unroll 16
        for (int d = 0; d < E_; d++)           // d ascending — order-critical
            acc = fmaf(et_s[d], buf[d * E_ + e], acc);
        float nv = fminf(5.0f, fmaxf(-5.0f, acc));
        out[((size_t)b * S_ + s) * E_ + e] = nv;

        __syncthreads();                       // all done reading buf & et_s
        et_s[e] = nv;
        if (e == 0 && s + STAGES < s_end) {
            mbar_expect_tx_(mb[slot], TILE_BYTES_R);
            bulk_g2s_((uint32_t)__cvta_generic_to_shared(&wa_buf[slot * O_]),
                      wa_base + (size_t)(s + STAGES) * O_, TILE_BYTES_R, mb[slot]);
        }
        __syncthreads();                       // et_s published
        v = nv;
    }

    g_et[b * E_ + e] = v;                      // exact fp32 pass-through
}

// ---------------------------------------------------------------------------
// Launch: round-13 schedule shape (wa serialized on default stream; recur
// chained on one secondary stream, gated per-launch on the matching wa event).
// Only change: 5-way wa split 1184/1184/1184/296/248 (same 14 waves) adds a
// gating milestone at s=480, shrinking the exposed recur tail 80 -> 32 steps.
// ---------------------------------------------------------------------------
extern "C" void kernel_launch(void* const* d_in, const int* in_sizes, int n_in,
                              void* d_out, int out_size) {
    const float* X  = (const float*)d_in[0];   // [8,512,128]
    const float* W1 = (const float*)d_in[1];   // [512,128]
    const float* b1 = (const float*)d_in[2];   // [512]
    const float* W2 = (const float*)d_in[3];   // [16384,512]
    const float* b2 = (const float*)d_in[4];   // [16384]
    const float* e0 = (const float*)d_in[5];   // [1,128]
    float* out = (float*)d_out;                // [8,512,128] float32

    static cudaStream_t s2 = nullptr;
    static cudaEvent_t  ev_wa[NWL];
    static cudaEvent_t  ev_join;
    if (s2 == nullptr) {
        cudaStreamCreateWithFlags(&s2, cudaStreamNonBlocking);
        for (int c = 0; c < NWL; c++)
            cudaEventCreateWithFlags(&ev_wa[c], cudaEventDisableTiming);
        cudaEventCreateWithFlags(&ev_join, cudaEventDisableTiming);
        cudaFuncSetAttribute(hidden_kernel,
                             cudaFuncAttributeMaxDynamicSharedMemorySize, HID_SMEM);
        cudaFuncSetAttribute(recur_kernel,
                             cudaFuncAttributeMaxDynamicSharedMemorySize,
                             STAGES * TILE_BYTES_R);
    }

    hidden_kernel<<<BS_ / HROWS, 512, HID_SMEM>>>(X, W1, b1);

    for (int c = 0; c < NWL; c++) {
        wa_kernel<<<WA_COUNT[c], 256>>>(W2, b2, WA_BASE[c]);
        cudaEventRecord(ev_wa[c], 0);
    }
    for (int c = 0; c < NWL; c++) {
        cudaStreamWaitEvent(s2, ev_wa[c], 0);
        recur_kernel<<<B_, E_, STAGES * TILE_BYTES_R, s2>>>(e0, out, RS[c], RS[c + 1]);
    }
    cudaEventRecord(ev_join, s2);
    cudaStreamWaitEvent(0, ev_join, 0);
}